// round 4
// baseline (speedup 1.0000x reference)
#include <cuda_runtime.h>
#include <math.h>

#define DIMC 128
#define NMAX 50000
#define MMAX 2500
#define CAP  2048
#define MAXK 32
#define KNN  8
#define SCALE 0.17677669529663687f  // 1/sqrt(32)

// ---------------- scratch (__device__ globals; no allocation allowed) -------
__device__ float4 g_center[MMAX];
__device__ int    g_ccnt[MMAX];
__device__ float  g_cfeat[MMAX * DIMC];
__device__ int    g_cand_idx[MMAX * CAP];
__device__ float  g_cand_dist[MMAX * CAP];
__device__ int    g_nbr_idx[MMAX * MAXK];
__device__ int    g_nbr_cnt[MMAX];
__device__ float  g_q[MMAX * DIMC];
__device__ float  g_attnout[MMAX * DIMC];
__device__ float  g_upd[MMAX * DIMC];
__device__ float  g_cf1[MMAX * DIMC];
__device__ float  g_hid[MMAX * 4 * DIMC];
__device__ float  g_ffn[MMAX * DIMC];
__device__ float  g_cf[MMAX * DIMC];
__device__ float  g_kall[NMAX * DIMC];
__device__ float  g_vall[NMAX * DIMC];
__device__ int    g_knn_idx[NMAX * KNN];
__device__ float  g_knn_dist[NMAX * KNN];

// ---------------- gather centers + zero counters ----------------------------
__global__ void gather_kernel(const float* __restrict__ xyz,
                              const float* __restrict__ feats,
                              const int* __restrict__ idxc, int M) {
    int t = blockIdx.x * blockDim.x + threadIdx.x;
    if (t < M) {
        int n = idxc[t];
        float x = xyz[n * 3 + 0], y = xyz[n * 3 + 1], z = xyz[n * 3 + 2];
        g_center[t] = make_float4(x, y, z, x * x + y * y + z * z);
        g_ccnt[t] = 0;
    }
    if (t < M * DIMC) {
        int m = t >> 7, c = t & 127;
        g_cfeat[t] = feats[idxc[m] * DIMC + c];
    }
}

// ---------------- fused pair scan: ball candidates + knn top-8 -------------
__global__ void pair_scan_kernel(const float* __restrict__ xyz, int N, int M) {
    extern __shared__ float4 sc[];
    for (int i = threadIdx.x; i < M; i += blockDim.x) sc[i] = g_center[i];
    __syncthreads();
    int n = blockIdx.x * blockDim.x + threadIdx.x;
    if (n >= N) return;
    float x = xyz[n * 3 + 0], y = xyz[n * 3 + 1], z = xyz[n * 3 + 2];
    float s = x * x + y * y + z * z;

    float kd[KNN]; int ki[KNN];
#pragma unroll
    for (int i = 0; i < KNN; i++) { kd[i] = 3.0e38f; ki[i] = -1; }

    for (int m = 0; m < M; m++) {
        float4 c = sc[m];
        float dot = c.x * x + c.y * y + c.z * z;
        float d2 = (c.w + s) - 2.0f * dot;
        float dist = (d2 > 0.0f) ? sqrtf(d2) : 0.0f;
        if (dist < 0.3f) {
            int slot = atomicAdd(&g_ccnt[m], 1);
            if (slot < CAP) {
                g_cand_idx[m * CAP + slot] = n;
                g_cand_dist[m * CAP + slot] = dist;
            }
        }
        if (dist < kd[KNN - 1]) {
            float nd = dist; int ni = m;
#pragma unroll
            for (int i = 0; i < KNN; i++) {
                if (nd < kd[i]) {
                    float td = kd[i]; int ti = ki[i];
                    kd[i] = nd; ki[i] = ni; nd = td; ni = ti;
                }
            }
        }
    }
#pragma unroll
    for (int i = 0; i < KNN; i++) {
        g_knn_idx[n * KNN + i] = ki[i];
        g_knn_dist[n * KNN + i] = kd[i];
    }
}

// ---------------- per-center top-32 selection (stable ties by index) --------
__global__ void select_topk_kernel(int M) {
    int m = blockIdx.x;
    int tid = threadIdx.x;
    __shared__ float sd[CAP];
    __shared__ int   si[CAP];
    __shared__ float rd[256];
    __shared__ int   ri[256];
    __shared__ int   rp[256];
    int cnt = g_ccnt[m];
    if (cnt > CAP) cnt = CAP;
    for (int i = tid; i < cnt; i += blockDim.x) {
        sd[i] = g_cand_dist[m * CAP + i];
        si[i] = g_cand_idx[m * CAP + i];
    }
    __syncthreads();
    for (int r = 0; r < MAXK; r++) {
        float bd = 3.0e38f; int bi = 0x7fffffff; int bp = -1;
        for (int i = tid; i < cnt; i += blockDim.x) {
            float dd = sd[i]; int ii = si[i];
            if (dd < bd || (dd == bd && ii < bi)) { bd = dd; bi = ii; bp = i; }
        }
        rd[tid] = bd; ri[tid] = bi; rp[tid] = bp;
        __syncthreads();
        for (int st = 128; st > 0; st >>= 1) {
            if (tid < st) {
                if (rd[tid + st] < rd[tid] ||
                    (rd[tid + st] == rd[tid] && ri[tid + st] < ri[tid])) {
                    rd[tid] = rd[tid + st]; ri[tid] = ri[tid + st]; rp[tid] = rp[tid + st];
                }
            }
            __syncthreads();
        }
        if (tid == 0) {
            g_nbr_idx[m * MAXK + r] = (r < cnt) ? ri[0] : -1;
            if (rp[0] >= 0) sd[rp[0]] = 3.0e38f;
        }
        __syncthreads();
    }
    if (tid == 0) g_nbr_cnt[m] = (cnt < MAXK) ? cnt : MAXK;
}

// ---------------- fp32 tiled GEMM: C = A(MxK) @ B(KxN) [+bias][relu] --------
template <bool BIAS, bool RELU>
__global__ void gemm128_kernel(const float* __restrict__ A, const float* __restrict__ B,
                               const float* __restrict__ bias, float* __restrict__ C,
                               int Mr, int K, int Nc) {
    __shared__ float As[8][128];
    __shared__ float Bs[8][128];
    int bm = blockIdx.x * 128;
    int bn = blockIdx.y * 128;
    int tid = threadIdx.x;
    int ty = tid >> 4, tx = tid & 15;
    float acc[8][8];
#pragma unroll
    for (int i = 0; i < 8; i++)
#pragma unroll
        for (int j = 0; j < 8; j++) acc[i][j] = 0.0f;

    int arow = tid >> 1, akc = (tid & 1) * 4;
    int brow = tid >> 5, bcol = (tid & 31) * 4;

    for (int k0 = 0; k0 < K; k0 += 8) {
        float4 av = make_float4(0.f, 0.f, 0.f, 0.f);
        if (bm + arow < Mr) av = *(const float4*)&A[(size_t)(bm + arow) * K + k0 + akc];
        As[akc + 0][arow] = av.x; As[akc + 1][arow] = av.y;
        As[akc + 2][arow] = av.z; As[akc + 3][arow] = av.w;
        *(float4*)&Bs[brow][bcol] = *(const float4*)&B[(size_t)(k0 + brow) * Nc + bn + bcol];
        __syncthreads();
#pragma unroll
        for (int kk = 0; kk < 8; kk++) {
            float a[8], b[8];
            *(float4*)(a)     = *(float4*)&As[kk][ty * 8];
            *(float4*)(a + 4) = *(float4*)&As[kk][ty * 8 + 4];
            *(float4*)(b)     = *(float4*)&Bs[kk][tx * 8];
            *(float4*)(b + 4) = *(float4*)&Bs[kk][tx * 8 + 4];
#pragma unroll
            for (int i = 0; i < 8; i++)
#pragma unroll
                for (int j = 0; j < 8; j++) acc[i][j] += a[i] * b[j];
        }
        __syncthreads();
    }
#pragma unroll
    for (int i = 0; i < 8; i++) {
        int r = bm + ty * 8 + i;
        if (r < Mr) {
#pragma unroll
            for (int j = 0; j < 8; j += 4) {
                int c = bn + tx * 8 + j;
                float4 v;
                v.x = acc[i][j]; v.y = acc[i][j + 1]; v.z = acc[i][j + 2]; v.w = acc[i][j + 3];
                if (BIAS) { v.x += bias[c]; v.y += bias[c + 1]; v.z += bias[c + 2]; v.w += bias[c + 3]; }
                if (RELU) {
                    v.x = fmaxf(v.x, 0.f); v.y = fmaxf(v.y, 0.f);
                    v.z = fmaxf(v.z, 0.f); v.w = fmaxf(v.w, 0.f);
                }
                *(float4*)&C[(size_t)r * Nc + c] = v;
            }
        }
    }
}

// ---------------- per-center masked attention -------------------------------
__global__ void attn_kernel(int M) {
    int m = blockIdx.x;
    int t = threadIdx.x;  // 128 threads
    __shared__ float kb[MAXK * 129];
    __shared__ float vb[MAXK * 129];
    __shared__ float qs[128];
    __shared__ float at[128];
    __shared__ int   sidx[MAXK];
    int cnt = g_nbr_cnt[m];
    if (t < MAXK) sidx[t] = g_nbr_idx[m * MAXK + t];
    qs[t] = g_q[m * DIMC + t] * SCALE;
    __syncthreads();
    for (int j = 0; j < cnt; j++) {
        int idx = sidx[j];
        kb[j * 129 + t] = g_kall[(size_t)idx * DIMC + t];
        vb[j * 129 + t] = g_vall[(size_t)idx * DIMC + t];
    }
    __syncthreads();
    int h = t >> 5, j = t & 31;
    float sc;
    if (j < cnt) {
        const float* kr = &kb[j * 129 + h * 32];
        const float* qq = &qs[h * 32];
        float s = 0.f;
#pragma unroll
        for (int d = 0; d < 32; d++) s += qq[d] * kr[d];
        sc = s;
    } else {
        sc = -1e9f;
    }
    float mx = sc;
#pragma unroll
    for (int o = 16; o; o >>= 1) mx = fmaxf(mx, __shfl_xor_sync(0xffffffffu, mx, o));
    float e = expf(sc - mx);
    float sm = e;
#pragma unroll
    for (int o = 16; o; o >>= 1) sm += __shfl_xor_sync(0xffffffffu, sm, o);
    at[t] = e / sm;
    __syncthreads();
    // out_flat[t] with t = d*H + h  (swapaxes(1,2) layout)
    int h2 = t & 3, d2 = t >> 2;
    float o = 0.f;
    for (int jj = 0; jj < cnt; jj++) o += at[h2 * 32 + jj] * vb[jj * 129 + h2 * 32 + d2];
    g_attnout[m * DIMC + t] = o;
}

// ---------------- LayerNorm + residual --------------------------------------
__global__ void ln_res_kernel(const float* __restrict__ x, const float* __restrict__ resid,
                              const float* __restrict__ w, const float* __restrict__ b,
                              float* __restrict__ out, int Mr) {
    int row = blockIdx.x * 8 + (threadIdx.x >> 5);
    int lane = threadIdx.x & 31;
    if (row >= Mr) return;
    const float* xr = x + (size_t)row * DIMC;
    float v[4];
#pragma unroll
    for (int i = 0; i < 4; i++) v[i] = xr[lane + 32 * i];
    float s = v[0] + v[1] + v[2] + v[3];
#pragma unroll
    for (int o = 16; o; o >>= 1) s += __shfl_xor_sync(0xffffffffu, s, o);
    float mu = s * 0.0078125f;
    float s2 = 0.f;
#pragma unroll
    for (int i = 0; i < 4; i++) { float d = v[i] - mu; s2 += d * d; }
#pragma unroll
    for (int o = 16; o; o >>= 1) s2 += __shfl_xor_sync(0xffffffffu, s2, o);
    float r = rsqrtf(s2 * 0.0078125f + 1e-5f);
    const float* rr = resid + (size_t)row * DIMC;
    float* orow = out + (size_t)row * DIMC;
#pragma unroll
    for (int i = 0; i < 4; i++) {
        int c = lane + 32 * i;
        orow[c] = rr[c] + (v[i] - mu) * r * w[c] + b[c];
    }
}

// ---------------- KNN inverse-distance upsample + Wp head -------------------
__global__ void upsample_kernel(const float* __restrict__ feats, const float* __restrict__ Wp,
                                const float* __restrict__ bp, float* __restrict__ out, int N) {
    extern __shared__ float smem[];
    float* swp = smem;          // 128*128
    float* so  = smem + 16384;  // 128
    float* sw  = smem + 16512;  // 8
    int t = threadIdx.x;        // 128 threads
    for (int i = t; i < 16384; i += blockDim.x) swp[i] = Wp[i];
    __syncthreads();
    for (int n = blockIdx.x; n < N; n += gridDim.x) {
        if (t < KNN) {
            float dd = g_knn_dist[n * KNN + t] + 1e-6f;
            sw[t] = 1.0f / (dd * dd);
        }
        __syncthreads();
        float wsum = sw[0] + sw[1] + sw[2] + sw[3] + sw[4] + sw[5] + sw[6] + sw[7];
        float o = 0.f;
#pragma unroll
        for (int k = 0; k < KNN; k++) {
            int id = g_knn_idx[n * KNN + k];
            o += sw[k] * g_cf[(size_t)id * DIMC + t];
        }
        o *= (1.0f / wsum);
        so[t] = o;
        __syncthreads();
        float hacc = 0.f;
#pragma unroll 16
        for (int c = 0; c < DIMC; c++) hacc += so[c] * swp[c * DIMC + t];
        out[(size_t)n * DIMC + t] = feats[(size_t)n * DIMC + t] + o + fmaxf(hacc + bp[t], 0.f);
        __syncthreads();
    }
}

// ---------------- host launch ------------------------------------------------
static float* symf(const void* sym) { void* p = nullptr; cudaGetSymbolAddress(&p, sym); return (float*)p; }

extern "C" void kernel_launch(void* const* d_in, const int* in_sizes, int n_in,
                              void* d_out, int out_size) {
    const float* xyz  = (const float*)d_in[0];
    const float* feats= (const float*)d_in[1];
    const float* Wq   = (const float*)d_in[2];
    const float* Wk   = (const float*)d_in[3];
    const float* Wv   = (const float*)d_in[4];
    const float* Wo   = (const float*)d_in[5];
    const float* bo   = (const float*)d_in[6];
    const float* n1w  = (const float*)d_in[7];
    const float* n1b  = (const float*)d_in[8];
    const float* n2w  = (const float*)d_in[9];
    const float* n2b  = (const float*)d_in[10];
    const float* W1   = (const float*)d_in[11];
    const float* b1   = (const float*)d_in[12];
    const float* W2   = (const float*)d_in[13];
    const float* b2   = (const float*)d_in[14];
    const float* Wp   = (const float*)d_in[15];
    const float* bp   = (const float*)d_in[16];
    const int* idxc   = (const int*)d_in[17];
    float* out = (float*)d_out;

    int N = in_sizes[0] / 3;
    int M = in_sizes[17];

    float* p_cfeat = symf(g_cfeat);
    float* p_q     = symf(g_q);
    float* p_kall  = symf(g_kall);
    float* p_vall  = symf(g_vall);
    float* p_ao    = symf(g_attnout);
    float* p_upd   = symf(g_upd);
    float* p_cf1   = symf(g_cf1);
    float* p_hid   = symf(g_hid);
    float* p_ffn   = symf(g_ffn);
    float* p_cf    = symf(g_cf);

    gather_kernel<<<(M * DIMC + 255) / 256, 256>>>(xyz, feats, idxc, M);
    pair_scan_kernel<<<(N + 255) / 256, 256, M * sizeof(float4)>>>(xyz, N, M);
    select_topk_kernel<<<M, 256>>>(M);

    // projections
    gemm128_kernel<false, false><<<dim3((M + 127) / 128, 1), 256>>>(p_cfeat, Wq, nullptr, p_q, M, 128, 128);
    gemm128_kernel<false, false><<<dim3((N + 127) / 128, 1), 256>>>(feats, Wk, nullptr, p_kall, N, 128, 128);
    gemm128_kernel<false, false><<<dim3((N + 127) / 128, 1), 256>>>(feats, Wv, nullptr, p_vall, N, 128, 128);

    attn_kernel<<<M, 128>>>(M);

    gemm128_kernel<true, false><<<dim3((M + 127) / 128, 1), 256>>>(p_ao, Wo, bo, p_upd, M, 128, 128);
    ln_res_kernel<<<(M + 7) / 8, 256>>>(p_upd, p_cfeat, n1w, n1b, p_cf1, M);
    gemm128_kernel<true, true ><<<dim3((M + 127) / 128, 4), 256>>>(p_cf1, W1, b1, p_hid, M, 128, 512);
    gemm128_kernel<true, false><<<dim3((M + 127) / 128, 1), 256>>>(p_hid, W2, b2, p_ffn, M, 512, 128);
    ln_res_kernel<<<(M + 7) / 8, 256>>>(p_ffn, p_cf1, n2w, n2b, p_cf, M);

    int ups_smem = (16384 + 128 + 16) * sizeof(float);
    cudaFuncSetAttribute(upsample_kernel, cudaFuncAttributeMaxDynamicSharedMemorySize, ups_smem);
    upsample_kernel<<<444, 128, ups_smem>>>(feats, Wp, bp, out, N);
}

// round 5
// speedup vs baseline: 1.3899x; 1.3899x over previous
#include <cuda_runtime.h>
#include <math.h>

#define DIMC 128
#define NMAX 50000
#define MMAX 2500
#define CAP  2048
#define MAXK 32
#define KNN  8
#define SCALE 0.17677669529663687f  // 1/sqrt(32)

// spatial grid for center binning
#define GC   28
#define NCELL (GC*GC*GC)          // 21952
#define CELLH 0.45f
#define INVH  2.2222222222222223f
#define ORG  (-6.3f)

// ---------------- scratch (__device__ globals; no allocation allowed) -------
__device__ float4 g_center[MMAX];
__device__ int    g_ccell[MMAX];
__device__ int    g_ccnt[MMAX];
__device__ float  g_cfeat[MMAX * DIMC];
__device__ int    g_cand_idx[MMAX * CAP];
__device__ float  g_cand_dist[MMAX * CAP];
__device__ int    g_nbr_idx[MMAX * MAXK];
__device__ int    g_nbr_cnt[MMAX];
__device__ float  g_q[MMAX * DIMC];
__device__ float  g_attnout[MMAX * DIMC];
__device__ float  g_upd[MMAX * DIMC];
__device__ float  g_cf1[MMAX * DIMC];
__device__ float  g_hid[MMAX * 4 * DIMC];
__device__ float  g_ffn[MMAX * DIMC];
__device__ float  g_cf[MMAX * DIMC];
__device__ float  g_kall[NMAX * DIMC];   // later reused as U (interp output)
__device__ float  g_vall[NMAX * DIMC];   // later reused as relu(U@Wp+bp)
__device__ int    g_knn_idx[NMAX * KNN];
__device__ float  g_knn_dist[NMAX * KNN];
// binning
__device__ int    g_cellcnt[NCELL];
__device__ int    g_cellstart[NCELL + 1];
__device__ int    g_cellptr[NCELL];
__device__ float4 g_binc[MMAX];
__device__ int    g_binm[MMAX];

// ---------------- f32x2 packed-FMA helpers ----------------------------------
__device__ __forceinline__ void fma2(unsigned long long& d, unsigned long long a,
                                     unsigned long long b) {
    asm("fma.rn.f32x2 %0, %1, %2, %0;" : "+l"(d) : "l"(a), "l"(b));
}
__device__ __forceinline__ unsigned long long pack2(float v) {
    unsigned long long r;
    asm("mov.b64 %0, {%1, %1};" : "=l"(r) : "r"(__float_as_uint(v)));
    return r;
}
__device__ __forceinline__ float2 unpack2(unsigned long long a) {
    unsigned int lo, hi;
    asm("mov.b64 {%0, %1}, %2;" : "=r"(lo), "=r"(hi) : "l"(a));
    return make_float2(__uint_as_float(lo), __uint_as_float(hi));
}

// ---------------- gather centers + zero counters ----------------------------
__global__ void gather_kernel(const float* __restrict__ xyz,
                              const float* __restrict__ feats,
                              const int* __restrict__ idxc, int M) {
    int t = blockIdx.x * blockDim.x + threadIdx.x;
    if (t < M) {
        int n = idxc[t];
        float x = xyz[n * 3 + 0], y = xyz[n * 3 + 1], z = xyz[n * 3 + 2];
        g_center[t] = make_float4(x, y, z, x * x + y * y + z * z);
        g_ccnt[t] = 0;
        int ix = min(max((int)floorf((x - ORG) * INVH), 0), GC - 1);
        int iy = min(max((int)floorf((y - ORG) * INVH), 0), GC - 1);
        int iz = min(max((int)floorf((z - ORG) * INVH), 0), GC - 1);
        g_ccell[t] = (iz * GC + iy) * GC + ix;
    }
    if (t < M * DIMC) {
        int m = t >> 7, c = t & 127;
        g_cfeat[t] = feats[idxc[m] * DIMC + c];
    }
}

// ---------------- binning: count / scan / scatter ---------------------------
__global__ void bin_count_kernel(int M) {
    int m = blockIdx.x * blockDim.x + threadIdx.x;
    if (m < M) atomicAdd(&g_cellcnt[g_ccell[m]], 1);
}

__global__ void bin_scan_kernel() {
    __shared__ int part[1024];
    int t = threadIdx.x;
    const int PER = (NCELL + 1023) / 1024;  // 22
    int b0 = t * PER, b1 = min(b0 + PER, NCELL);
    int s = 0;
    for (int i = b0; i < b1; i++) s += g_cellcnt[i];
    part[t] = s;
    __syncthreads();
    for (int off = 1; off < 1024; off <<= 1) {
        int v = (t >= off) ? part[t - off] : 0;
        __syncthreads();
        part[t] += v;
        __syncthreads();
    }
    int run = (t == 0) ? 0 : part[t - 1];
    for (int i = b0; i < b1; i++) {
        int c = g_cellcnt[i];
        g_cellstart[i] = run;
        g_cellptr[i] = run;
        run += c;
    }
    if (t == 1023) g_cellstart[NCELL] = run;
}

__global__ void bin_scatter_kernel(int M) {
    int m = blockIdx.x * blockDim.x + threadIdx.x;
    if (m < M) {
        int slot = atomicAdd(&g_cellptr[g_ccell[m]], 1);
        g_binc[slot] = g_center[m];
        g_binm[slot] = m;
    }
}

// ---------------- per-cell scan helper ---------------------------------------
template <bool BALL>
__device__ __forceinline__ void scan_cell(int cid, float x, float y, float z, float s,
                                          int n, float kd[KNN], int ki[KNN]) {
    int c0 = g_cellstart[cid], c1 = g_cellstart[cid + 1];
    for (int j = c0; j < c1; j++) {
        float4 c = g_binc[j];
        float dot = c.x * x + c.y * y + c.z * z;
        float d2 = (c.w + s) - 2.0f * dot;
        if (BALL) {
            if (d2 < 0.0900001f) {
                float dist = (d2 > 0.0f) ? sqrtf(d2) : 0.0f;
                if (dist < 0.3f) {
                    int m = g_binm[j];
                    int slot = atomicAdd(&g_ccnt[m], 1);
                    if (slot < CAP) {
                        g_cand_idx[m * CAP + slot] = n;
                        g_cand_dist[m * CAP + slot] = dist;
                    }
                }
            }
        }
        if (d2 < kd[KNN - 1]) {
            float nd = d2;
            int ni = g_binm[j];
#pragma unroll
            for (int i = 0; i < KNN; i++) {
                if (nd < kd[i]) {
                    float td = kd[i]; int ti = ki[i];
                    kd[i] = nd; ki[i] = ni; nd = td; ni = ti;
                }
            }
        }
    }
}

// ---------------- point scan: ball candidates (27 cells) + exact KNN --------
__global__ void point_scan_kernel(const float* __restrict__ xyz, int N) {
    int n = blockIdx.x * blockDim.x + threadIdx.x;
    if (n >= N) return;
    float x = xyz[n * 3 + 0], y = xyz[n * 3 + 1], z = xyz[n * 3 + 2];
    float s = x * x + y * y + z * z;
    int ix = min(max((int)floorf((x - ORG) * INVH), 0), GC - 1);
    int iy = min(max((int)floorf((y - ORG) * INVH), 0), GC - 1);
    int iz = min(max((int)floorf((z - ORG) * INVH), 0), GC - 1);

    float kd[KNN]; int ki[KNN];
#pragma unroll
    for (int i = 0; i < KNN; i++) { kd[i] = 3.0e38f; ki[i] = -1; }

    // R=1 cube: exact ball coverage (cell 0.45 > radius 0.3) + KNN seed
    for (int dz = -1; dz <= 1; dz++) {
        int jz = iz + dz; if (jz < 0 || jz >= GC) continue;
        for (int dy = -1; dy <= 1; dy++) {
            int jy = iy + dy; if (jy < 0 || jy >= GC) continue;
            for (int dx = -1; dx <= 1; dx++) {
                int jx = ix + dx; if (jx < 0 || jx >= GC) continue;
                scan_cell<true>((jz * GC + jy) * GC + jx, x, y, z, s, n, kd, ki);
            }
        }
    }
    // expand shells until the 8th-best beats the guaranteed-covered radius
    int R = 1;
    while (true) {
        float rx = fminf(x - (ORG + (ix - R) * CELLH), (ORG + (ix + R + 1) * CELLH) - x);
        float ry = fminf(y - (ORG + (iy - R) * CELLH), (ORG + (iy + R + 1) * CELLH) - y);
        float rz = fminf(z - (ORG + (iz - R) * CELLH), (ORG + (iz + R + 1) * CELLH) - z);
        float rc = fminf(rx, fminf(ry, rz));
        if (rc > 0.0f && kd[KNN - 1] < rc * rc) break;
        if (R >= GC) break;
        R++;
        for (int dz = -R; dz <= R; dz++) {
            int jz = iz + dz; if (jz < 0 || jz >= GC) continue;
            bool zf = (dz == -R) || (dz == R);
            for (int dy = -R; dy <= R; dy++) {
                int jy = iy + dy; if (jy < 0 || jy >= GC) continue;
                bool yf = (dy == -R) || (dy == R);
                if (zf || yf) {
                    for (int dx = -R; dx <= R; dx++) {
                        int jx = ix + dx; if (jx < 0 || jx >= GC) continue;
                        scan_cell<false>((jz * GC + jy) * GC + jx, x, y, z, s, n, kd, ki);
                    }
                } else {
                    int jx = ix - R;
                    if (jx >= 0) scan_cell<false>((jz * GC + jy) * GC + jx, x, y, z, s, n, kd, ki);
                    jx = ix + R;
                    if (jx < GC) scan_cell<false>((jz * GC + jy) * GC + jx, x, y, z, s, n, kd, ki);
                }
            }
        }
    }
#pragma unroll
    for (int i = 0; i < KNN; i++) {
        float d2 = kd[i];
        g_knn_idx[n * KNN + i] = ki[i];
        g_knn_dist[n * KNN + i] = (d2 > 0.0f) ? sqrtf(d2) : 0.0f;
    }
}

// ---------------- per-center top-32 selection (stable ties by index) --------
__global__ void select_topk_kernel(int M) {
    int m = blockIdx.x;
    int tid = threadIdx.x;  // 128
    __shared__ float sd[CAP];
    __shared__ int   si[CAP];
    __shared__ float rd[128];
    __shared__ int   ri[128];
    __shared__ int   rp[128];
    int cnt = g_ccnt[m];
    if (cnt > CAP) cnt = CAP;
    for (int i = tid; i < cnt; i += blockDim.x) {
        sd[i] = g_cand_dist[m * CAP + i];
        si[i] = g_cand_idx[m * CAP + i];
    }
    __syncthreads();
    for (int r = 0; r < MAXK; r++) {
        float bd = 3.0e38f; int bi = 0x7fffffff; int bp = -1;
        for (int i = tid; i < cnt; i += blockDim.x) {
            float dd = sd[i]; int ii = si[i];
            if (dd < bd || (dd == bd && ii < bi)) { bd = dd; bi = ii; bp = i; }
        }
        rd[tid] = bd; ri[tid] = bi; rp[tid] = bp;
        __syncthreads();
        for (int st = 64; st > 0; st >>= 1) {
            if (tid < st) {
                if (rd[tid + st] < rd[tid] ||
                    (rd[tid + st] == rd[tid] && ri[tid + st] < ri[tid])) {
                    rd[tid] = rd[tid + st]; ri[tid] = ri[tid + st]; rp[tid] = rp[tid + st];
                }
            }
            __syncthreads();
        }
        if (tid == 0) {
            g_nbr_idx[m * MAXK + r] = (r < cnt) ? ri[0] : -1;
            if (rp[0] >= 0) sd[rp[0]] = 3.0e38f;
        }
        __syncthreads();
    }
    if (tid == 0) g_nbr_cnt[m] = (cnt < MAXK) ? cnt : MAXK;
}

// ---------------- fp32 tiled GEMM 128x128 tile, f32x2 FMAs ------------------
template <bool BIAS, bool RELU>
__global__ void gemm128_kernel(const float* __restrict__ A, const float* __restrict__ B,
                               const float* __restrict__ bias, float* __restrict__ C,
                               int Mr, int K, int Nc) {
    __shared__ float As[8][128];
    __shared__ float Bs[8][128];
    int bm = blockIdx.x * 128;
    int bn = blockIdx.y * 128;
    int tid = threadIdx.x;
    int ty = tid >> 4, tx = tid & 15;
    unsigned long long acc2[8][4];
#pragma unroll
    for (int i = 0; i < 8; i++)
#pragma unroll
        for (int j = 0; j < 4; j++) acc2[i][j] = 0ull;

    int arow = tid >> 1, akc = (tid & 1) * 4;
    int brow = tid >> 5, bcol = (tid & 31) * 4;

    for (int k0 = 0; k0 < K; k0 += 8) {
        float4 av = make_float4(0.f, 0.f, 0.f, 0.f);
        if (bm + arow < Mr) av = *(const float4*)&A[(size_t)(bm + arow) * K + k0 + akc];
        As[akc + 0][arow] = av.x; As[akc + 1][arow] = av.y;
        As[akc + 2][arow] = av.z; As[akc + 3][arow] = av.w;
        *(float4*)&Bs[brow][bcol] = *(const float4*)&B[(size_t)(k0 + brow) * Nc + bn + bcol];
        __syncthreads();
#pragma unroll
        for (int kk = 0; kk < 8; kk++) {
            float a[8];
            *(float4*)(a)     = *(float4*)&As[kk][ty * 8];
            *(float4*)(a + 4) = *(float4*)&As[kk][ty * 8 + 4];
            ulonglong2 bq0 = *(const ulonglong2*)&Bs[kk][tx * 8];
            ulonglong2 bq1 = *(const ulonglong2*)&Bs[kk][tx * 8 + 4];
#pragma unroll
            for (int i = 0; i < 8; i++) {
                unsigned long long ai = pack2(a[i]);
                fma2(acc2[i][0], ai, bq0.x);
                fma2(acc2[i][1], ai, bq0.y);
                fma2(acc2[i][2], ai, bq1.x);
                fma2(acc2[i][3], ai, bq1.y);
            }
        }
        __syncthreads();
    }
#pragma unroll
    for (int i = 0; i < 8; i++) {
        int r = bm + ty * 8 + i;
        if (r < Mr) {
#pragma unroll
            for (int jq = 0; jq < 2; jq++) {
                int c = bn + tx * 8 + jq * 4;
                float2 v0 = unpack2(acc2[i][jq * 2 + 0]);
                float2 v1 = unpack2(acc2[i][jq * 2 + 1]);
                float4 v = make_float4(v0.x, v0.y, v1.x, v1.y);
                if (BIAS) { v.x += bias[c]; v.y += bias[c + 1]; v.z += bias[c + 2]; v.w += bias[c + 3]; }
                if (RELU) {
                    v.x = fmaxf(v.x, 0.f); v.y = fmaxf(v.y, 0.f);
                    v.z = fmaxf(v.z, 0.f); v.w = fmaxf(v.w, 0.f);
                }
                *(float4*)&C[(size_t)r * Nc + c] = v;
            }
        }
    }
}

// ---------------- fp32 tiled GEMM 32x128 tile (small M, high occupancy) -----
template <bool BIAS, bool RELU>
__global__ void gemm32_kernel(const float* __restrict__ A, const float* __restrict__ B,
                              const float* __restrict__ bias, float* __restrict__ C,
                              int Mr, int K, int Nc) {
    __shared__ float As[8][33];
    __shared__ float Bs[8][128];
    int bm = blockIdx.x * 32;
    int bn = blockIdx.y * 128;
    int tid = threadIdx.x;
    int ty = tid >> 5, tx = tid & 31;  // 8 x 32 thread grid, each 4x4 outputs
    unsigned long long acc2[4][2];
#pragma unroll
    for (int i = 0; i < 4; i++) { acc2[i][0] = 0ull; acc2[i][1] = 0ull; }

    int arow = tid >> 3, acol = tid & 7;
    int brow = tid >> 5, bcol = (tid & 31) * 4;

    for (int k0 = 0; k0 < K; k0 += 8) {
        float av = 0.f;
        if (bm + arow < Mr) av = A[(size_t)(bm + arow) * K + k0 + acol];
        As[acol][arow] = av;
        *(float4*)&Bs[brow][bcol] = *(const float4*)&B[(size_t)(k0 + brow) * Nc + bn + bcol];
        __syncthreads();
#pragma unroll
        for (int kk = 0; kk < 8; kk++) {
            ulonglong2 bq = *(const ulonglong2*)&Bs[kk][tx * 4];
#pragma unroll
            for (int i = 0; i < 4; i++) {
                unsigned long long ai = pack2(As[kk][ty * 4 + i]);
                fma2(acc2[i][0], ai, bq.x);
                fma2(acc2[i][1], ai, bq.y);
            }
        }
        __syncthreads();
    }
#pragma unroll
    for (int i = 0; i < 4; i++) {
        int r = bm + ty * 4 + i;
        if (r < Mr) {
            int c = bn + tx * 4;
            float2 v0 = unpack2(acc2[i][0]);
            float2 v1 = unpack2(acc2[i][1]);
            float4 v = make_float4(v0.x, v0.y, v1.x, v1.y);
            if (BIAS) { v.x += bias[c]; v.y += bias[c + 1]; v.z += bias[c + 2]; v.w += bias[c + 3]; }
            if (RELU) {
                v.x = fmaxf(v.x, 0.f); v.y = fmaxf(v.y, 0.f);
                v.z = fmaxf(v.z, 0.f); v.w = fmaxf(v.w, 0.f);
            }
            *(float4*)&C[(size_t)r * Nc + c] = v;
        }
    }
}

// ---------------- per-center masked attention -------------------------------
__global__ void attn_kernel(int M) {
    int m = blockIdx.x;
    int t = threadIdx.x;  // 128 threads
    __shared__ float kb[MAXK * 129];
    __shared__ float vb[MAXK * 129];
    __shared__ float qs[128];
    __shared__ float at[128];
    __shared__ int   sidx[MAXK];
    int cnt = g_nbr_cnt[m];
    if (t < MAXK) sidx[t] = g_nbr_idx[m * MAXK + t];
    qs[t] = g_q[m * DIMC + t] * SCALE;
    __syncthreads();
    for (int j = 0; j < cnt; j++) {
        int idx = sidx[j];
        kb[j * 129 + t] = g_kall[(size_t)idx * DIMC + t];
        vb[j * 129 + t] = g_vall[(size_t)idx * DIMC + t];
    }
    __syncthreads();
    int h = t >> 5, j = t & 31;
    float sc;
    if (j < cnt) {
        const float* kr = &kb[j * 129 + h * 32];
        const float* qq = &qs[h * 32];
        float s = 0.f;
#pragma unroll
        for (int d = 0; d < 32; d++) s += qq[d] * kr[d];
        sc = s;
    } else {
        sc = -1e9f;
    }
    float mx = sc;
#pragma unroll
    for (int o = 16; o; o >>= 1) mx = fmaxf(mx, __shfl_xor_sync(0xffffffffu, mx, o));
    float e = expf(sc - mx);
    float sm = e;
#pragma unroll
    for (int o = 16; o; o >>= 1) sm += __shfl_xor_sync(0xffffffffu, sm, o);
    at[t] = e / sm;
    __syncthreads();
    int h2 = t & 3, d2 = t >> 2;
    float o = 0.f;
    for (int jj = 0; jj < cnt; jj++) o += at[h2 * 32 + jj] * vb[jj * 129 + h2 * 32 + d2];
    g_attnout[m * DIMC + t] = o;
}

// ---------------- LayerNorm + residual --------------------------------------
__global__ void ln_res_kernel(const float* __restrict__ x, const float* __restrict__ resid,
                              const float* __restrict__ w, const float* __restrict__ b,
                              float* __restrict__ out, int Mr) {
    int row = blockIdx.x * 8 + (threadIdx.x >> 5);
    int lane = threadIdx.x & 31;
    if (row >= Mr) return;
    const float* xr = x + (size_t)row * DIMC;
    float v[4];
#pragma unroll
    for (int i = 0; i < 4; i++) v[i] = xr[lane + 32 * i];
    float s = v[0] + v[1] + v[2] + v[3];
#pragma unroll
    for (int o = 16; o; o >>= 1) s += __shfl_xor_sync(0xffffffffu, s, o);
    float mu = s * 0.0078125f;
    float s2 = 0.f;
#pragma unroll
    for (int i = 0; i < 4; i++) { float d = v[i] - mu; s2 += d * d; }
#pragma unroll
    for (int o = 16; o; o >>= 1) s2 += __shfl_xor_sync(0xffffffffu, s2, o);
    float r = rsqrtf(s2 * 0.0078125f + 1e-5f);
    const float* rr = resid + (size_t)row * DIMC;
    float* orow = out + (size_t)row * DIMC;
#pragma unroll
    for (int i = 0; i < 4; i++) {
        int c = lane + 32 * i;
        orow[c] = rr[c] + (v[i] - mu) * r * w[c] + b[c];
    }
}

// ---------------- KNN inverse-distance interpolation ------------------------
__global__ void interp_kernel(float* __restrict__ U, int N) {
    int gt = blockIdx.x * blockDim.x + threadIdx.x;
    int p = gt >> 5, lane = gt & 31;
    if (p >= N) return;
    float w[KNN]; int id[KNN];
    float wsum = 0.f;
#pragma unroll
    for (int k = 0; k < KNN; k++) {
        id[k] = g_knn_idx[p * KNN + k];
        float d = g_knn_dist[p * KNN + k] + 1e-6f;
        w[k] = 1.0f / (d * d);
        wsum += w[k];
    }
    float inv = 1.0f / wsum;
    float4 acc = make_float4(0.f, 0.f, 0.f, 0.f);
#pragma unroll
    for (int k = 0; k < KNN; k++) {
        float4 v = *(const float4*)&g_cf[(size_t)id[k] * DIMC + lane * 4];
        acc.x += w[k] * v.x; acc.y += w[k] * v.y;
        acc.z += w[k] * v.z; acc.w += w[k] * v.w;
    }
    acc.x *= inv; acc.y *= inv; acc.z *= inv; acc.w *= inv;
    *(float4*)&U[(size_t)p * DIMC + lane * 4] = acc;
}

// ---------------- final: out = feats + U + relu_out -------------------------
__global__ void final_add_kernel(const float* __restrict__ feats,
                                 const float* __restrict__ U,
                                 const float* __restrict__ Hr,
                                 float* __restrict__ out, int total4) {
    int i = blockIdx.x * blockDim.x + threadIdx.x;
    if (i >= total4) return;
    float4 f = *(const float4*)&feats[i * 4];
    float4 u = *(const float4*)&U[i * 4];
    float4 h = *(const float4*)&Hr[i * 4];
    f.x += u.x + h.x; f.y += u.y + h.y; f.z += u.z + h.z; f.w += u.w + h.w;
    *(float4*)&out[i * 4] = f;
}

// ---------------- host launch ------------------------------------------------
static float* symf(const void* sym) { void* p = nullptr; cudaGetSymbolAddress(&p, sym); return (float*)p; }
static int*   symi(const void* sym) { void* p = nullptr; cudaGetSymbolAddress(&p, sym); return (int*)p; }

extern "C" void kernel_launch(void* const* d_in, const int* in_sizes, int n_in,
                              void* d_out, int out_size) {
    const float* xyz  = (const float*)d_in[0];
    const float* feats= (const float*)d_in[1];
    const float* Wq   = (const float*)d_in[2];
    const float* Wk   = (const float*)d_in[3];
    const float* Wv   = (const float*)d_in[4];
    const float* Wo   = (const float*)d_in[5];
    const float* bo   = (const float*)d_in[6];
    const float* n1w  = (const float*)d_in[7];
    const float* n1b  = (const float*)d_in[8];
    const float* n2w  = (const float*)d_in[9];
    const float* n2b  = (const float*)d_in[10];
    const float* W1   = (const float*)d_in[11];
    const float* b1   = (const float*)d_in[12];
    const float* W2   = (const float*)d_in[13];
    const float* b2   = (const float*)d_in[14];
    const float* Wp   = (const float*)d_in[15];
    const float* bp   = (const float*)d_in[16];
    const int* idxc   = (const int*)d_in[17];
    float* out = (float*)d_out;

    int N = in_sizes[0] / 3;
    int M = in_sizes[17];

    float* p_cfeat = symf(g_cfeat);
    float* p_q     = symf(g_q);
    float* p_kall  = symf(g_kall);
    float* p_vall  = symf(g_vall);
    float* p_ao    = symf(g_attnout);
    float* p_upd   = symf(g_upd);
    float* p_cf1   = symf(g_cf1);
    float* p_hid   = symf(g_hid);
    float* p_ffn   = symf(g_ffn);
    float* p_cf    = symf(g_cf);
    int*   p_ccnt  = symi(g_cellcnt);

    cudaMemsetAsync(p_ccnt, 0, NCELL * sizeof(int));
    gather_kernel<<<(M * DIMC + 255) / 256, 256>>>(xyz, feats, idxc, M);
    bin_count_kernel<<<(M + 255) / 256, 256>>>(M);
    bin_scan_kernel<<<1, 1024>>>();
    bin_scatter_kernel<<<(M + 255) / 256, 256>>>(M);
    point_scan_kernel<<<(N + 255) / 256, 256>>>(xyz, N);
    select_topk_kernel<<<M, 128>>>(M);

    // projections
    gemm32_kernel<false, false><<<dim3((M + 31) / 32, 1), 256>>>(p_cfeat, Wq, nullptr, p_q, M, 128, 128);
    gemm128_kernel<false, false><<<dim3((N + 127) / 128, 1), 256>>>(feats, Wk, nullptr, p_kall, N, 128, 128);
    gemm128_kernel<false, false><<<dim3((N + 127) / 128, 1), 256>>>(feats, Wv, nullptr, p_vall, N, 128, 128);

    attn_kernel<<<M, 128>>>(M);

    gemm32_kernel<true, false><<<dim3((M + 31) / 32, 1), 256>>>(p_ao, Wo, bo, p_upd, M, 128, 128);
    ln_res_kernel<<<(M + 7) / 8, 256>>>(p_upd, p_cfeat, n1w, n1b, p_cf1, M);
    gemm32_kernel<true, true ><<<dim3((M + 31) / 32, 4), 256>>>(p_cf1, W1, b1, p_hid, M, 128, 512);
    gemm32_kernel<true, false><<<dim3((M + 31) / 32, 1), 256>>>(p_hid, W2, b2, p_ffn, M, 512, 128);
    ln_res_kernel<<<(M + 7) / 8, 256>>>(p_ffn, p_cf1, n2w, n2b, p_cf, M);

    // upsample: interp -> U (g_kall), Hr = relu(U@Wp+bp) (g_vall), out = feats+U+Hr
    interp_kernel<<<(N * 32 + 255) / 256, 256>>>(p_kall, N);
    gemm128_kernel<true, true><<<dim3((N + 127) / 128, 1), 256>>>(p_kall, Wp, bp, p_vall, N, 128, 128);
    final_add_kernel<<<(N * DIMC / 4 + 255) / 256, 256>>>(feats, p_kall, p_vall, out, N * DIMC / 4);
}

// round 6
// speedup vs baseline: 1.7362x; 1.2492x over previous
#include <cuda_runtime.h>
#include <math.h>

#define DIMC 128
#define NMAX 50000
#define MMAX 2500
#define CAP  2048
#define MAXK 32
#define KNN  8
#define SCALE 0.17677669529663687f  // 1/sqrt(32)

// spatial grid
#define GC   28
#define NCELL (GC*GC*GC)          // 21952
#define CELLH 0.45f
#define INVH  2.2222222222222223f
#define ORG  (-6.3f)

// ---------------- scratch (__device__ globals; no allocation allowed) -------
__device__ float4 g_center[MMAX];
__device__ int    g_ccell[MMAX];
__device__ int    g_ccnt[MMAX];
__device__ float  g_cfeat[MMAX * DIMC];
__device__ int    g_cand_idx[MMAX * CAP];
__device__ float  g_cand_dist[MMAX * CAP];
__device__ int    g_nbr_idx[MMAX * MAXK];
__device__ int    g_nbr_cnt[MMAX];
__device__ float  g_q[MMAX * DIMC];
__device__ float  g_attnout[MMAX * DIMC];
__device__ float  g_upd[MMAX * DIMC];
__device__ float  g_cf1[MMAX * DIMC];
__device__ float  g_hid[MMAX * 4 * DIMC];
__device__ float  g_ffn[MMAX * DIMC];
__device__ float  g_cf[MMAX * DIMC];
__device__ float  g_kall[NMAX * DIMC];   // later reused as U (interp output)
__device__ float  g_vall[NMAX * DIMC];
__device__ int    g_knn_idx[NMAX * KNN];
__device__ float  g_knn_dist[NMAX * KNN];
// center binning
__device__ int    g_cellcnt[NCELL];
__device__ int    g_cellstart[NCELL + 1];
__device__ int    g_cellptr[NCELL];
__device__ float4 g_binc[MMAX];
__device__ int    g_binm[MMAX];
// point sorting
__device__ int    g_pcellcnt[NCELL];
__device__ int    g_pcellstart[NCELL + 1];
__device__ int    g_pcellptr[NCELL];
__device__ float4 g_pxyz[NMAX];
__device__ int    g_psort[NMAX];

// ---------------- f32x2 packed-FMA helpers ----------------------------------
__device__ __forceinline__ void fma2(unsigned long long& d, unsigned long long a,
                                     unsigned long long b) {
    asm("fma.rn.f32x2 %0, %1, %2, %0;" : "+l"(d) : "l"(a), "l"(b));
}
__device__ __forceinline__ unsigned long long pack2(float v) {
    unsigned long long r;
    asm("mov.b64 %0, {%1, %1};" : "=l"(r) : "r"(__float_as_uint(v)));
    return r;
}
__device__ __forceinline__ float2 unpack2(unsigned long long a) {
    unsigned int lo, hi;
    asm("mov.b64 {%0, %1}, %2;" : "=r"(lo), "=r"(hi) : "l"(a));
    return make_float2(__uint_as_float(lo), __uint_as_float(hi));
}

// ---------------- gather centers + zero counters ----------------------------
__global__ void gather_kernel(const float* __restrict__ xyz,
                              const float* __restrict__ feats,
                              const int* __restrict__ idxc, int M) {
    int t = blockIdx.x * blockDim.x + threadIdx.x;
    if (t < M) {
        int n = idxc[t];
        float x = xyz[n * 3 + 0], y = xyz[n * 3 + 1], z = xyz[n * 3 + 2];
        g_center[t] = make_float4(x, y, z, x * x + y * y + z * z);
        g_ccnt[t] = 0;
        int ix = min(max((int)floorf((x - ORG) * INVH), 0), GC - 1);
        int iy = min(max((int)floorf((y - ORG) * INVH), 0), GC - 1);
        int iz = min(max((int)floorf((z - ORG) * INVH), 0), GC - 1);
        g_ccell[t] = (iz * GC + iy) * GC + ix;
    }
    if (t < M * DIMC) {
        int m = t >> 7, c = t & 127;
        g_cfeat[t] = feats[idxc[m] * DIMC + c];
    }
}

// ---------------- binning: count / scan / scatter ---------------------------
__global__ void bin_count_kernel(int M) {
    int m = blockIdx.x * blockDim.x + threadIdx.x;
    if (m < M) atomicAdd(&g_cellcnt[g_ccell[m]], 1);
}

__global__ void scan_cells_kernel(const int* __restrict__ cnt, int* __restrict__ start,
                                  int* __restrict__ ptr, int ncell) {
    __shared__ int part[1024];
    int t = threadIdx.x;
    int PER = (ncell + 1023) / 1024;
    int b0 = t * PER, b1 = min(b0 + PER, ncell);
    int s = 0;
    for (int i = b0; i < b1; i++) s += cnt[i];
    part[t] = s;
    __syncthreads();
    for (int off = 1; off < 1024; off <<= 1) {
        int v = (t >= off) ? part[t - off] : 0;
        __syncthreads();
        part[t] += v;
        __syncthreads();
    }
    int run = (t == 0) ? 0 : part[t - 1];
    for (int i = b0; i < b1; i++) {
        int c = cnt[i];
        start[i] = run;
        ptr[i] = run;
        run += c;
    }
    if (t == 1023) start[ncell] = run;
}

__global__ void bin_scatter_kernel(int M) {
    int m = blockIdx.x * blockDim.x + threadIdx.x;
    if (m < M) {
        int slot = atomicAdd(&g_cellptr[g_ccell[m]], 1);
        g_binc[slot] = g_center[m];
        g_binm[slot] = m;
    }
}

// ---------------- point sort by cell ----------------------------------------
__global__ void point_cell_kernel(const float* __restrict__ xyz, int N) {
    int n = blockIdx.x * blockDim.x + threadIdx.x;
    if (n >= N) return;
    float x = xyz[n * 3 + 0], y = xyz[n * 3 + 1], z = xyz[n * 3 + 2];
    int ix = min(max((int)floorf((x - ORG) * INVH), 0), GC - 1);
    int iy = min(max((int)floorf((y - ORG) * INVH), 0), GC - 1);
    int iz = min(max((int)floorf((z - ORG) * INVH), 0), GC - 1);
    atomicAdd(&g_pcellcnt[(iz * GC + iy) * GC + ix], 1);
}

__global__ void point_scatter_kernel(const float* __restrict__ xyz, int N) {
    int n = blockIdx.x * blockDim.x + threadIdx.x;
    if (n >= N) return;
    float x = xyz[n * 3 + 0], y = xyz[n * 3 + 1], z = xyz[n * 3 + 2];
    int ix = min(max((int)floorf((x - ORG) * INVH), 0), GC - 1);
    int iy = min(max((int)floorf((y - ORG) * INVH), 0), GC - 1);
    int iz = min(max((int)floorf((z - ORG) * INVH), 0), GC - 1);
    int slot = atomicAdd(&g_pcellptr[(iz * GC + iy) * GC + ix], 1);
    g_pxyz[slot] = make_float4(x, y, z, x * x + y * y + z * z);
    g_psort[slot] = n;
}

// ---------------- per-cell scan helper ---------------------------------------
template <bool BALL>
__device__ __forceinline__ void scan_cell(int cid, float x, float y, float z, float s,
                                          int n, float kd[KNN], int ki[KNN]) {
    int c0 = g_cellstart[cid], c1 = g_cellstart[cid + 1];
    for (int j = c0; j < c1; j++) {
        float4 c = g_binc[j];
        float dot = c.x * x + c.y * y + c.z * z;
        float d2 = (c.w + s) - 2.0f * dot;
        if (BALL) {
            if (d2 < 0.0900001f) {
                float dist = (d2 > 0.0f) ? sqrtf(d2) : 0.0f;
                if (dist < 0.3f) {
                    int m = g_binm[j];
                    int slot = atomicAdd(&g_ccnt[m], 1);
                    if (slot < CAP) {
                        g_cand_idx[m * CAP + slot] = n;
                        g_cand_dist[m * CAP + slot] = dist;
                    }
                }
            }
        }
        if (d2 < kd[KNN - 1]) {
            float nd = d2;
            int ni = g_binm[j];
#pragma unroll
            for (int i = 0; i < KNN; i++) {
                if (nd < kd[i]) {
                    float td = kd[i]; int ti = ki[i];
                    kd[i] = nd; ki[i] = ni; nd = td; ni = ti;
                }
            }
        }
    }
}

// ---------------- point scan over SORTED points: ball + exact KNN -----------
__global__ void point_scan_kernel(int N) {
    int t = blockIdx.x * blockDim.x + threadIdx.x;
    if (t >= N) return;
    float4 p = g_pxyz[t];
    int n = g_psort[t];
    float x = p.x, y = p.y, z = p.z, s = p.w;
    int ix = min(max((int)floorf((x - ORG) * INVH), 0), GC - 1);
    int iy = min(max((int)floorf((y - ORG) * INVH), 0), GC - 1);
    int iz = min(max((int)floorf((z - ORG) * INVH), 0), GC - 1);

    float kd[KNN]; int ki[KNN];
#pragma unroll
    for (int i = 0; i < KNN; i++) { kd[i] = 3.0e38f; ki[i] = -1; }

    // R=1 cube: exact ball coverage (cell 0.45 > radius 0.3) + KNN seed
    for (int dz = -1; dz <= 1; dz++) {
        int jz = iz + dz; if (jz < 0 || jz >= GC) continue;
        for (int dy = -1; dy <= 1; dy++) {
            int jy = iy + dy; if (jy < 0 || jy >= GC) continue;
            for (int dx = -1; dx <= 1; dx++) {
                int jx = ix + dx; if (jx < 0 || jx >= GC) continue;
                scan_cell<true>((jz * GC + jy) * GC + jx, x, y, z, s, n, kd, ki);
            }
        }
    }
    // expand shells until 8th-best beats the guaranteed-covered radius
    int R = 1;
    while (true) {
        float rx = fminf(x - (ORG + (ix - R) * CELLH), (ORG + (ix + R + 1) * CELLH) - x);
        float ry = fminf(y - (ORG + (iy - R) * CELLH), (ORG + (iy + R + 1) * CELLH) - y);
        float rz = fminf(z - (ORG + (iz - R) * CELLH), (ORG + (iz + R + 1) * CELLH) - z);
        float rc = fminf(rx, fminf(ry, rz));
        if (rc > 0.0f && kd[KNN - 1] < rc * rc) break;
        if (R >= GC) break;
        R++;
        for (int dz = -R; dz <= R; dz++) {
            int jz = iz + dz; if (jz < 0 || jz >= GC) continue;
            bool zf = (dz == -R) || (dz == R);
            for (int dy = -R; dy <= R; dy++) {
                int jy = iy + dy; if (jy < 0 || jy >= GC) continue;
                bool yf = (dy == -R) || (dy == R);
                if (zf || yf) {
                    for (int dx = -R; dx <= R; dx++) {
                        int jx = ix + dx; if (jx < 0 || jx >= GC) continue;
                        scan_cell<false>((jz * GC + jy) * GC + jx, x, y, z, s, n, kd, ki);
                    }
                } else {
                    int jx = ix - R;
                    if (jx >= 0) scan_cell<false>((jz * GC + jy) * GC + jx, x, y, z, s, n, kd, ki);
                    jx = ix + R;
                    if (jx < GC) scan_cell<false>((jz * GC + jy) * GC + jx, x, y, z, s, n, kd, ki);
                }
            }
        }
    }
#pragma unroll
    for (int i = 0; i < KNN; i++) {
        float d2 = kd[i];
        g_knn_idx[n * KNN + i] = ki[i];
        g_knn_dist[n * KNN + i] = (d2 > 0.0f) ? sqrtf(d2) : 0.0f;
    }
}

// ---------------- per-center top-32 selection (stable ties by index) --------
__global__ void select_topk_kernel(int M) {
    int m = blockIdx.x;
    int tid = threadIdx.x;  // 128
    __shared__ float sd[CAP];
    __shared__ int   si[CAP];
    __shared__ float rd[128];
    __shared__ int   ri[128];
    __shared__ int   rp[128];
    int cnt = g_ccnt[m];
    if (cnt > CAP) cnt = CAP;
    for (int i = tid; i < cnt; i += blockDim.x) {
        sd[i] = g_cand_dist[m * CAP + i];
        si[i] = g_cand_idx[m * CAP + i];
    }
    __syncthreads();
    for (int r = 0; r < MAXK; r++) {
        float bd = 3.0e38f; int bi = 0x7fffffff; int bp = -1;
        for (int i = tid; i < cnt; i += blockDim.x) {
            float dd = sd[i]; int ii = si[i];
            if (dd < bd || (dd == bd && ii < bi)) { bd = dd; bi = ii; bp = i; }
        }
        rd[tid] = bd; ri[tid] = bi; rp[tid] = bp;
        __syncthreads();
        for (int st = 64; st > 0; st >>= 1) {
            if (tid < st) {
                if (rd[tid + st] < rd[tid] ||
                    (rd[tid + st] == rd[tid] && ri[tid + st] < ri[tid])) {
                    rd[tid] = rd[tid + st]; ri[tid] = ri[tid + st]; rp[tid] = rp[tid + st];
                }
            }
            __syncthreads();
        }
        if (tid == 0) {
            g_nbr_idx[m * MAXK + r] = (r < cnt) ? ri[0] : -1;
            if (rp[0] >= 0) sd[rp[0]] = 3.0e38f;
        }
        __syncthreads();
    }
    if (tid == 0) g_nbr_cnt[m] = (cnt < MAXK) ? cnt : MAXK;
}

// ---------------- fp32 tiled GEMM 128x128 tile, f32x2 FMAs ------------------
// FINAL: C = F + A + relu(acc + bias)   (fused upsample tail; Nc must equal K layout rows)
template <bool BIAS, bool RELU, bool FINAL>
__global__ void gemm128_kernel(const float* __restrict__ A, const float* __restrict__ B,
                               const float* __restrict__ bias, float* __restrict__ C,
                               const float* __restrict__ F,
                               int Mr, int K, int Nc) {
    __shared__ float As[8][128];
    __shared__ float Bs[8][128];
    int bm = blockIdx.x * 128;
    int bn = blockIdx.y * 128;
    int tid = threadIdx.x;
    int ty = tid >> 4, tx = tid & 15;
    unsigned long long acc2[8][4];
#pragma unroll
    for (int i = 0; i < 8; i++)
#pragma unroll
        for (int j = 0; j < 4; j++) acc2[i][j] = 0ull;

    int arow = tid >> 1, akc = (tid & 1) * 4;
    int brow = tid >> 5, bcol = (tid & 31) * 4;

    for (int k0 = 0; k0 < K; k0 += 8) {
        float4 av = make_float4(0.f, 0.f, 0.f, 0.f);
        if (bm + arow < Mr) av = *(const float4*)&A[(size_t)(bm + arow) * K + k0 + akc];
        As[akc + 0][arow] = av.x; As[akc + 1][arow] = av.y;
        As[akc + 2][arow] = av.z; As[akc + 3][arow] = av.w;
        *(float4*)&Bs[brow][bcol] = *(const float4*)&B[(size_t)(k0 + brow) * Nc + bn + bcol];
        __syncthreads();
#pragma unroll
        for (int kk = 0; kk < 8; kk++) {
            float a[8];
            *(float4*)(a)     = *(float4*)&As[kk][ty * 8];
            *(float4*)(a + 4) = *(float4*)&As[kk][ty * 8 + 4];
            ulonglong2 bq0 = *(const ulonglong2*)&Bs[kk][tx * 8];
            ulonglong2 bq1 = *(const ulonglong2*)&Bs[kk][tx * 8 + 4];
#pragma unroll
            for (int i = 0; i < 8; i++) {
                unsigned long long ai = pack2(a[i]);
                fma2(acc2[i][0], ai, bq0.x);
                fma2(acc2[i][1], ai, bq0.y);
                fma2(acc2[i][2], ai, bq1.x);
                fma2(acc2[i][3], ai, bq1.y);
            }
        }
        __syncthreads();
    }
#pragma unroll
    for (int i = 0; i < 8; i++) {
        int r = bm + ty * 8 + i;
        if (r < Mr) {
#pragma unroll
            for (int jq = 0; jq < 2; jq++) {
                int c = bn + tx * 8 + jq * 4;
                float2 v0 = unpack2(acc2[i][jq * 2 + 0]);
                float2 v1 = unpack2(acc2[i][jq * 2 + 1]);
                float4 v = make_float4(v0.x, v0.y, v1.x, v1.y);
                if (BIAS) { v.x += bias[c]; v.y += bias[c + 1]; v.z += bias[c + 2]; v.w += bias[c + 3]; }
                if (RELU) {
                    v.x = fmaxf(v.x, 0.f); v.y = fmaxf(v.y, 0.f);
                    v.z = fmaxf(v.z, 0.f); v.w = fmaxf(v.w, 0.f);
                }
                if (FINAL) {
                    float4 f = *(const float4*)&F[(size_t)r * Nc + c];
                    float4 u = *(const float4*)&A[(size_t)r * Nc + c];
                    v.x += f.x + u.x; v.y += f.y + u.y;
                    v.z += f.z + u.z; v.w += f.w + u.w;
                }
                *(float4*)&C[(size_t)r * Nc + c] = v;
            }
        }
    }
}

// ---------------- fp32 tiled GEMM 32x128 tile (small M, high occupancy) -----
template <bool BIAS, bool RELU>
__global__ void gemm32_kernel(const float* __restrict__ A, const float* __restrict__ B,
                              const float* __restrict__ bias, float* __restrict__ C,
                              int Mr, int K, int Nc) {
    __shared__ float As[8][33];
    __shared__ float Bs[8][128];
    int bm = blockIdx.x * 32;
    int bn = blockIdx.y * 128;
    int tid = threadIdx.x;
    int ty = tid >> 5, tx = tid & 31;
    unsigned long long acc2[4][2];
#pragma unroll
    for (int i = 0; i < 4; i++) { acc2[i][0] = 0ull; acc2[i][1] = 0ull; }

    int arow = tid >> 3, acol = tid & 7;
    int brow = tid >> 5, bcol = (tid & 31) * 4;

    for (int k0 = 0; k0 < K; k0 += 8) {
        float av = 0.f;
        if (bm + arow < Mr) av = A[(size_t)(bm + arow) * K + k0 + acol];
        As[acol][arow] = av;
        *(float4*)&Bs[brow][bcol] = *(const float4*)&B[(size_t)(k0 + brow) * Nc + bn + bcol];
        __syncthreads();
#pragma unroll
        for (int kk = 0; kk < 8; kk++) {
            ulonglong2 bq = *(const ulonglong2*)&Bs[kk][tx * 4];
#pragma unroll
            for (int i = 0; i < 4; i++) {
                unsigned long long ai = pack2(As[kk][ty * 4 + i]);
                fma2(acc2[i][0], ai, bq.x);
                fma2(acc2[i][1], ai, bq.y);
            }
        }
        __syncthreads();
    }
#pragma unroll
    for (int i = 0; i < 4; i++) {
        int r = bm + ty * 4 + i;
        if (r < Mr) {
            int c = bn + tx * 4;
            float2 v0 = unpack2(acc2[i][0]);
            float2 v1 = unpack2(acc2[i][1]);
            float4 v = make_float4(v0.x, v0.y, v1.x, v1.y);
            if (BIAS) { v.x += bias[c]; v.y += bias[c + 1]; v.z += bias[c + 2]; v.w += bias[c + 3]; }
            if (RELU) {
                v.x = fmaxf(v.x, 0.f); v.y = fmaxf(v.y, 0.f);
                v.z = fmaxf(v.z, 0.f); v.w = fmaxf(v.w, 0.f);
            }
            *(float4*)&C[(size_t)r * Nc + c] = v;
        }
    }
}

// ---------------- per-center masked attention -------------------------------
__global__ void attn_kernel(int M) {
    int m = blockIdx.x;
    int t = threadIdx.x;  // 128 threads
    __shared__ float kb[MAXK * 129];
    __shared__ float vb[MAXK * 129];
    __shared__ float qs[128];
    __shared__ float at[128];
    __shared__ int   sidx[MAXK];
    int cnt = g_nbr_cnt[m];
    if (t < MAXK) sidx[t] = g_nbr_idx[m * MAXK + t];
    qs[t] = g_q[m * DIMC + t] * SCALE;
    __syncthreads();
    for (int j = 0; j < cnt; j++) {
        int idx = sidx[j];
        kb[j * 129 + t] = g_kall[(size_t)idx * DIMC + t];
        vb[j * 129 + t] = g_vall[(size_t)idx * DIMC + t];
    }
    __syncthreads();
    int h = t >> 5, j = t & 31;
    float sc;
    if (j < cnt) {
        const float* kr = &kb[j * 129 + h * 32];
        const float* qq = &qs[h * 32];
        float s = 0.f;
#pragma unroll
        for (int d = 0; d < 32; d++) s += qq[d] * kr[d];
        sc = s;
    } else {
        sc = -1e9f;
    }
    float mx = sc;
#pragma unroll
    for (int o = 16; o; o >>= 1) mx = fmaxf(mx, __shfl_xor_sync(0xffffffffu, mx, o));
    float e = expf(sc - mx);
    float sm = e;
#pragma unroll
    for (int o = 16; o; o >>= 1) sm += __shfl_xor_sync(0xffffffffu, sm, o);
    at[t] = e / sm;
    __syncthreads();
    int h2 = t & 3, d2 = t >> 2;
    float o = 0.f;
    for (int jj = 0; jj < cnt; jj++) o += at[h2 * 32 + jj] * vb[jj * 129 + h2 * 32 + d2];
    g_attnout[m * DIMC + t] = o;
}

// ---------------- LayerNorm + residual --------------------------------------
__global__ void ln_res_kernel(const float* __restrict__ x, const float* __restrict__ resid,
                              const float* __restrict__ w, const float* __restrict__ b,
                              float* __restrict__ out, int Mr) {
    int row = blockIdx.x * 8 + (threadIdx.x >> 5);
    int lane = threadIdx.x & 31;
    if (row >= Mr) return;
    const float* xr = x + (size_t)row * DIMC;
    float v[4];
#pragma unroll
    for (int i = 0; i < 4; i++) v[i] = xr[lane + 32 * i];
    float s = v[0] + v[1] + v[2] + v[3];
#pragma unroll
    for (int o = 16; o; o >>= 1) s += __shfl_xor_sync(0xffffffffu, s, o);
    float mu = s * 0.0078125f;
    float s2 = 0.f;
#pragma unroll
    for (int i = 0; i < 4; i++) { float d = v[i] - mu; s2 += d * d; }
#pragma unroll
    for (int o = 16; o; o >>= 1) s2 += __shfl_xor_sync(0xffffffffu, s2, o);
    float r = rsqrtf(s2 * 0.0078125f + 1e-5f);
    const float* rr = resid + (size_t)row * DIMC;
    float* orow = out + (size_t)row * DIMC;
#pragma unroll
    for (int i = 0; i < 4; i++) {
        int c = lane + 32 * i;
        orow[c] = rr[c] + (v[i] - mu) * r * w[c] + b[c];
    }
}

// ---------------- KNN inverse-distance interpolation ------------------------
__global__ void interp_kernel(float* __restrict__ U, int N) {
    int gt = blockIdx.x * blockDim.x + threadIdx.x;
    int p = gt >> 5, lane = gt & 31;
    if (p >= N) return;
    float w[KNN]; int id[KNN];
    float wsum = 0.f;
#pragma unroll
    for (int k = 0; k < KNN; k++) {
        id[k] = g_knn_idx[p * KNN + k];
        float d = g_knn_dist[p * KNN + k] + 1e-6f;
        w[k] = 1.0f / (d * d);
        wsum += w[k];
    }
    float inv = 1.0f / wsum;
    float4 acc = make_float4(0.f, 0.f, 0.f, 0.f);
#pragma unroll
    for (int k = 0; k < KNN; k++) {
        float4 v = *(const float4*)&g_cf[(size_t)id[k] * DIMC + lane * 4];
        acc.x += w[k] * v.x; acc.y += w[k] * v.y;
        acc.z += w[k] * v.z; acc.w += w[k] * v.w;
    }
    acc.x *= inv; acc.y *= inv; acc.z *= inv; acc.w *= inv;
    *(float4*)&U[(size_t)p * DIMC + lane * 4] = acc;
}

// ---------------- host launch ------------------------------------------------
static float* symf(const void* sym) { void* p = nullptr; cudaGetSymbolAddress(&p, sym); return (float*)p; }
static int*   symi(const void* sym) { void* p = nullptr; cudaGetSymbolAddress(&p, sym); return (int*)p; }

extern "C" void kernel_launch(void* const* d_in, const int* in_sizes, int n_in,
                              void* d_out, int out_size) {
    const float* xyz  = (const float*)d_in[0];
    const float* feats= (const float*)d_in[1];
    const float* Wq   = (const float*)d_in[2];
    const float* Wk   = (const float*)d_in[3];
    const float* Wv   = (const float*)d_in[4];
    const float* Wo   = (const float*)d_in[5];
    const float* bo   = (const float*)d_in[6];
    const float* n1w  = (const float*)d_in[7];
    const float* n1b  = (const float*)d_in[8];
    const float* n2w  = (const float*)d_in[9];
    const float* n2b  = (const float*)d_in[10];
    const float* W1   = (const float*)d_in[11];
    const float* b1   = (const float*)d_in[12];
    const float* W2   = (const float*)d_in[13];
    const float* b2   = (const float*)d_in[14];
    const float* Wp   = (const float*)d_in[15];
    const float* bp   = (const float*)d_in[16];
    const int* idxc   = (const int*)d_in[17];
    float* out = (float*)d_out;

    int N = in_sizes[0] / 3;
    int M = in_sizes[17];

    float* p_cfeat = symf(g_cfeat);
    float* p_q     = symf(g_q);
    float* p_kall  = symf(g_kall);
    float* p_vall  = symf(g_vall);
    float* p_ao    = symf(g_attnout);
    float* p_upd   = symf(g_upd);
    float* p_cf1   = symf(g_cf1);
    float* p_hid   = symf(g_hid);
    float* p_ffn   = symf(g_ffn);
    float* p_cf    = symf(g_cf);
    int*   p_ccnt  = symi(g_cellcnt);
    int*   p_cstart= symi(g_cellstart);
    int*   p_cptr  = symi(g_cellptr);
    int*   p_pcnt  = symi(g_pcellcnt);
    int*   p_pstart= symi(g_pcellstart);
    int*   p_pptr  = symi(g_pcellptr);

    // lazy-created capture-fork resources (host objects; no device allocation)
    static cudaStream_t s2 = nullptr;
    static cudaEvent_t evFork = nullptr, evJoin = nullptr, evGather = nullptr;
    if (s2 == nullptr) {
        cudaStreamCreateWithFlags(&s2, cudaStreamNonBlocking);
        cudaEventCreateWithFlags(&evFork, cudaEventDisableTiming);
        cudaEventCreateWithFlags(&evJoin, cudaEventDisableTiming);
        cudaEventCreateWithFlags(&evGather, cudaEventDisableTiming);
    }
    bool fork = (s2 != nullptr && evFork != nullptr && evJoin != nullptr && evGather != nullptr);
    cudaStream_t sg = fork ? s2 : (cudaStream_t)0;  // gemm branch stream

    cudaMemsetAsync(p_ccnt, 0, NCELL * sizeof(int));
    cudaMemsetAsync(p_pcnt, 0, NCELL * sizeof(int));

    if (fork) {
        cudaEventRecord(evFork, 0);
        cudaStreamWaitEvent(s2, evFork, 0);
    }

    // ---- branch B (s2): big K/V projections, then Wq after gather ----
    gemm128_kernel<false, false, false><<<dim3((N + 127) / 128, 1), 256, 0, sg>>>(
        feats, Wk, nullptr, p_kall, nullptr, N, 128, 128);
    gemm128_kernel<false, false, false><<<dim3((N + 127) / 128, 1), 256, 0, sg>>>(
        feats, Wv, nullptr, p_vall, nullptr, N, 128, 128);

    // ---- branch A (default): gather + binning + sorted point scan ----
    gather_kernel<<<(M * DIMC + 255) / 256, 256>>>(xyz, feats, idxc, M);
    if (fork) {
        cudaEventRecord(evGather, 0);
        cudaStreamWaitEvent(s2, evGather, 0);
    }
    gemm32_kernel<false, false><<<dim3((M + 31) / 32, 1), 256, 0, sg>>>(
        p_cfeat, Wq, nullptr, p_q, M, 128, 128);

    bin_count_kernel<<<(M + 255) / 256, 256>>>(M);
    scan_cells_kernel<<<1, 1024>>>(p_ccnt, p_cstart, p_cptr, NCELL);
    bin_scatter_kernel<<<(M + 255) / 256, 256>>>(M);
    point_cell_kernel<<<(N + 255) / 256, 256>>>(xyz, N);
    scan_cells_kernel<<<1, 1024>>>(p_pcnt, p_pstart, p_pptr, NCELL);
    point_scatter_kernel<<<(N + 255) / 256, 256>>>(xyz, N);
    point_scan_kernel<<<(N + 255) / 256, 256>>>(N);
    select_topk_kernel<<<M, 128>>>(M);

    // ---- join ----
    if (fork) {
        cudaEventRecord(evJoin, s2);
        cudaStreamWaitEvent(0, evJoin, 0);
    }

    attn_kernel<<<M, 128>>>(M);

    gemm32_kernel<true, false><<<dim3((M + 31) / 32, 1), 256>>>(p_ao, Wo, bo, p_upd, M, 128, 128);
    ln_res_kernel<<<(M + 7) / 8, 256>>>(p_upd, p_cfeat, n1w, n1b, p_cf1, M);
    gemm32_kernel<true, true ><<<dim3((M + 31) / 32, 4), 256>>>(p_cf1, W1, b1, p_hid, M, 128, 512);
    gemm32_kernel<true, false><<<dim3((M + 31) / 32, 1), 256>>>(p_hid, W2, b2, p_ffn, M, 512, 128);
    ln_res_kernel<<<(M + 7) / 8, 256>>>(p_ffn, p_cf1, n2w, n2b, p_cf, M);

    // upsample: interp -> U (g_kall); fused gemm: out = feats + U + relu(U@Wp + bp)
    interp_kernel<<<(N * 32 + 255) / 256, 256>>>(p_kall, N);
    gemm128_kernel<true, true, true><<<dim3((N + 127) / 128, 1), 256>>>(
        p_kall, Wp, bp, out, feats, N, 128, 128);
}